// round 1
// baseline (speedup 1.0000x reference)
#include <cuda_runtime.h>
#include <math.h>

// YOLOv1 loss: S=14, B=2, C=20, N=30, BATCH=4096
// cells = 4096*14*14 = 802816
#define NCELLS        802816
#define CELLS_PER_BLK 128
#define NBLOCKS       (NCELLS / CELLS_PER_BLK)   // 6272 exact
#define FPC           30                          // floats per cell
#define PAD           31                          // smem row stride (coprime with 32 banks)
#define INV_S         (1.0f / 14.0f)

__device__ double g_partials[NBLOCKS];

__global__ __launch_bounds__(CELLS_PER_BLK) void yolo_main(
    const float* __restrict__ pred, const float* __restrict__ targ)
{
    __shared__ float sp[CELLS_PER_BLK * PAD];
    __shared__ float st[CELLS_PER_BLK * PAD];

    const int tid = threadIdx.x;
    const long long base = (long long)blockIdx.x * (CELLS_PER_BLK * FPC); // 3840 floats
    const float4* __restrict__ pv = reinterpret_cast<const float4*>(pred + base);
    const float4* __restrict__ tv = reinterpret_cast<const float4*>(targ + base);

    // ---- cooperative coalesced load: 960 float4 per array ----
    const int NV4 = CELLS_PER_BLK * FPC / 4; // 960
    for (int i = tid; i < NV4; i += CELLS_PER_BLK) {
        float4 a = pv[i];
        float4 b = tv[i];
        float av[4] = {a.x, a.y, a.z, a.w};
        float bv[4] = {b.x, b.y, b.z, b.w};
        int e = i * 4;
        #pragma unroll
        for (int j = 0; j < 4; ++j) {
            int ee = e + j;
            int c  = ee / FPC;          // magic-number div
            int k  = ee - c * FPC;
            sp[c * PAD + k] = av[j];
            st[c * PAD + k] = bv[j];
        }
    }
    __syncthreads();

    // ---- per-cell loss (one thread per cell) ----
    const float* __restrict__ p = &sp[tid * PAD];
    const float* __restrict__ t = &st[tid * PAD];

    const bool obj = t[4] > 0.0f;

    // target box (both tiled boxes identical -> use box 0)
    float tcx = t[0] * INV_S, tcy = t[1] * INV_S;
    float thw = 0.5f * t[2],  thh = 0.5f * t[3];
    float tx0 = tcx - thw, ty0 = tcy - thh;
    float tx1 = tcx + thw, ty1 = tcy + thh;
    float area_t = (tx1 - tx0) * (ty1 - ty0);

    float iou0, iou1;
    #pragma unroll
    for (int b = 0; b < 2; ++b) {
        const float* pb = p + 5 * b;
        float pcx = pb[0] * INV_S, pcy = pb[1] * INV_S;
        float phw = 0.5f * pb[2],  phh = 0.5f * pb[3];
        float px0 = pcx - phw, py0 = pcy - phh;
        float px1 = pcx + phw, py1 = pcy + phh;
        float ltx = fmaxf(px0, tx0), lty = fmaxf(py0, ty0);
        float rbx = fminf(px1, tx1), rby = fminf(py1, ty1);
        float wi = fmaxf(rbx - ltx, 0.0f);
        float hi = fmaxf(rby - lty, 0.0f);
        float inter  = wi * hi;
        float area_p = (px1 - px0) * (py1 - py0);
        float v = inter / (area_p + area_t - inter);
        if (b == 0) iou0 = v; else iou1 = v;
    }

    float loss;
    if (obj) {
        // argmax tie-break -> index 0 (matches jnp.argmax)
        int   r    = (iou1 > iou0) ? 1 : 0;
        float miou = fmaxf(iou0, iou1);
        const float* pb = p + 5 * r;

        float dx = pb[0] - t[0];
        float dy = pb[1] - t[1];
        float dxy = dx * dx + dy * dy;

        float dw = sqrtf(pb[2]) - sqrtf(t[2]);
        float dh = sqrtf(pb[3]) - sqrtf(t[3]);
        float dwh = dw * dw + dh * dh;

        float dob = pb[4] - miou;

        float cls = 0.0f;
        #pragma unroll
        for (int c = 0; c < 20; ++c) {
            float d = p[10 + c] - t[10 + c];
            cls += d * d;
        }
        loss = 5.0f * (dxy + dwh) + dob * dob + cls;
    } else {
        // noobj: both boxes' confidence vs target conf (0 here)
        float d0 = p[4] - t[4];
        float d1 = p[9] - t[9];
        loss = 0.5f * (d0 * d0 + d1 * d1);
    }

    // ---- block reduce in double (deterministic per-block partial) ----
    double s = (double)loss;
    #pragma unroll
    for (int o = 16; o > 0; o >>= 1)
        s += __shfl_down_sync(0xFFFFFFFFu, s, o);

    __shared__ double wsum[CELLS_PER_BLK / 32];
    int warp = tid >> 5, lane = tid & 31;
    if (lane == 0) wsum[warp] = s;
    __syncthreads();
    if (warp == 0) {
        double v = (lane < CELLS_PER_BLK / 32) ? wsum[lane] : 0.0;
        #pragma unroll
        for (int o = 2; o > 0; o >>= 1)
            v += __shfl_down_sync(0xFFFFFFFFu, v, o);
        if (lane == 0) g_partials[blockIdx.x] = v;
    }
}

__global__ __launch_bounds__(256) void yolo_final(float* __restrict__ out)
{
    double s = 0.0;
    for (int i = threadIdx.x; i < NBLOCKS; i += 256)
        s += g_partials[i];

    #pragma unroll
    for (int o = 16; o > 0; o >>= 1)
        s += __shfl_down_sync(0xFFFFFFFFu, s, o);

    __shared__ double wsum[8];
    int warp = threadIdx.x >> 5, lane = threadIdx.x & 31;
    if (lane == 0) wsum[warp] = s;
    __syncthreads();
    if (warp == 0) {
        double v = (lane < 8) ? wsum[lane] : 0.0;
        #pragma unroll
        for (int o = 4; o > 0; o >>= 1)
            v += __shfl_down_sync(0xFFFFFFFFu, v, o);
        if (lane == 0) out[0] = (float)(v * (1.0 / 4096.0));
    }
}

extern "C" void kernel_launch(void* const* d_in, const int* in_sizes, int n_in,
                              void* d_out, int out_size)
{
    const float* pred = (const float*)d_in[0];
    const float* targ = (const float*)d_in[1];
    yolo_main<<<NBLOCKS, CELLS_PER_BLK>>>(pred, targ);
    yolo_final<<<1, 256>>>((float*)d_out);
}

// round 2
// speedup vs baseline: 1.2532x; 1.2532x over previous
#include <cuda_runtime.h>
#include <math.h>

// YOLOv1 loss: S=14, B=2, C=20, N=30, BATCH=4096
// cells = 4096*14*14 = 802816
#define NCELLS        802816
#define CELLS_PER_BLK 128
#define NBLOCKS       (NCELLS / CELLS_PER_BLK)   // 6272 exact
#define FPC           30                          // floats per cell
#define INV_S         (1.0f / 14.0f)
#define NV4           (CELLS_PER_BLK * FPC / 4)   // 960 float4 per array

// partials as float, float4-aligned for vector loads in the final kernel
__device__ float4 g_partials4[NBLOCKS / 4];       // 1568 float4 = 6272 floats

__global__ __launch_bounds__(CELLS_PER_BLK) void yolo_main(
    const float* __restrict__ pred, const float* __restrict__ targ)
{
    // linear layout: sp = floats [0, 3840), st = floats [3840, 7680)
    __shared__ float4 s4[2 * NV4];                // 30720 B

    const int tid = threadIdx.x;
    const long long base = (long long)blockIdx.x * (CELLS_PER_BLK * FPC);
    const float4* __restrict__ pv = reinterpret_cast<const float4*>(pred + base);
    const float4* __restrict__ tv = reinterpret_cast<const float4*>(targ + base);

    // ---- pure linear copy: no index math between loads -> max MLP ----
    #pragma unroll
    for (int k = 0; k < NV4 / CELLS_PER_BLK; ++k) {       // 7 full rounds
        int i = tid + k * CELLS_PER_BLK;
        s4[i]       = __ldcs(&pv[i]);
        s4[NV4 + i] = __ldcs(&tv[i]);
    }
    {   // tail: 960 = 7*128 + 64
        int i = tid + 7 * CELLS_PER_BLK;
        if (i < NV4) {
            s4[i]       = __ldcs(&pv[i]);
            s4[NV4 + i] = __ldcs(&tv[i]);
        }
    }
    __syncthreads();

    // ---- per-cell loss (one thread per cell), stride-30 smem reads ----
    const float* __restrict__ p = reinterpret_cast<const float*>(s4) + tid * FPC;
    const float* __restrict__ t = reinterpret_cast<const float*>(s4) + 4 * NV4 + tid * FPC;

    const bool obj = t[4] > 0.0f;

    // target box (both tiled boxes identical -> use box 0)
    float tcx = t[0] * INV_S, tcy = t[1] * INV_S;
    float thw = 0.5f * t[2],  thh = 0.5f * t[3];
    float tx0 = tcx - thw, ty0 = tcy - thh;
    float tx1 = tcx + thw, ty1 = tcy + thh;
    float area_t = (tx1 - tx0) * (ty1 - ty0);

    float iou0, iou1;
    #pragma unroll
    for (int b = 0; b < 2; ++b) {
        const float* pb = p + 5 * b;
        float pcx = pb[0] * INV_S, pcy = pb[1] * INV_S;
        float phw = 0.5f * pb[2],  phh = 0.5f * pb[3];
        float px0 = pcx - phw, py0 = pcy - phh;
        float px1 = pcx + phw, py1 = pcy + phh;
        float ltx = fmaxf(px0, tx0), lty = fmaxf(py0, ty0);
        float rbx = fminf(px1, tx1), rby = fminf(py1, ty1);
        float wi = fmaxf(rbx - ltx, 0.0f);
        float hi = fmaxf(rby - lty, 0.0f);
        float inter  = wi * hi;
        float area_p = (px1 - px0) * (py1 - py0);
        float v = inter / (area_p + area_t - inter);
        if (b == 0) iou0 = v; else iou1 = v;
    }

    float loss;
    if (obj) {
        // argmax tie-break -> index 0 (matches jnp.argmax)
        int   r    = (iou1 > iou0) ? 1 : 0;
        float miou = fmaxf(iou0, iou1);
        const float* pb = p + 5 * r;

        float dx = pb[0] - t[0];
        float dy = pb[1] - t[1];
        float dxy = dx * dx + dy * dy;

        float dw = sqrtf(pb[2]) - sqrtf(t[2]);
        float dh = sqrtf(pb[3]) - sqrtf(t[3]);
        float dwh = dw * dw + dh * dh;

        float dob = pb[4] - miou;

        float cls = 0.0f;
        #pragma unroll
        for (int c = 0; c < 20; ++c) {
            float d = p[10 + c] - t[10 + c];
            cls += d * d;
        }
        loss = 5.0f * (dxy + dwh) + dob * dob + cls;
    } else {
        float d0 = p[4] - t[4];
        float d1 = p[9] - t[9];
        loss = 0.5f * (d0 * d0 + d1 * d1);
    }

    // ---- deterministic block reduce (fp32; per-block magnitude ~1e2) ----
    float s = loss;
    #pragma unroll
    for (int o = 16; o > 0; o >>= 1)
        s += __shfl_down_sync(0xFFFFFFFFu, s, o);

    __shared__ float wsum[CELLS_PER_BLK / 32];
    int warp = tid >> 5, lane = tid & 31;
    if (lane == 0) wsum[warp] = s;
    __syncthreads();
    if (warp == 0) {
        float v = (lane < CELLS_PER_BLK / 32) ? wsum[lane] : 0.0f;
        #pragma unroll
        for (int o = 2; o > 0; o >>= 1)
            v += __shfl_down_sync(0xFFFFFFFFu, v, o);
        if (lane == 0)
            reinterpret_cast<float*>(g_partials4)[blockIdx.x] = v;
    }
}

__global__ __launch_bounds__(1024) void yolo_final(float* __restrict__ out)
{
    const int NP4 = NBLOCKS / 4;   // 1568
    float s = 0.0f;
    for (int i = threadIdx.x; i < NP4; i += 1024) {
        float4 v = g_partials4[i];
        s += (v.x + v.y) + (v.z + v.w);
    }

    #pragma unroll
    for (int o = 16; o > 0; o >>= 1)
        s += __shfl_down_sync(0xFFFFFFFFu, s, o);

    __shared__ float wsum[32];
    int warp = threadIdx.x >> 5, lane = threadIdx.x & 31;
    if (lane == 0) wsum[warp] = s;
    __syncthreads();
    if (warp == 0) {
        float v = (lane < 32) ? wsum[lane] : 0.0f;
        #pragma unroll
        for (int o = 16; o > 0; o >>= 1)
            v += __shfl_down_sync(0xFFFFFFFFu, v, o);
        if (lane == 0) out[0] = v * (1.0f / 4096.0f);
    }
}

extern "C" void kernel_launch(void* const* d_in, const int* in_sizes, int n_in,
                              void* d_out, int out_size)
{
    const float* pred = (const float*)d_in[0];
    const float* targ = (const float*)d_in[1];
    yolo_main<<<NBLOCKS, CELLS_PER_BLK>>>(pred, targ);
    yolo_final<<<1, 1024>>>((float*)d_out);
}